// round 14
// baseline (speedup 1.0000x reference)
#include <cuda_runtime.h>
#include <cuda_bf16.h>
#include <math.h>
#include <stdint.h>

// Problem constants
#define BB 128
#define SS 1024
#define IND 256
#define DD 128
#define MM 64
#define OUTD 128
#define NROWS (BB * SS)   // 131072

// Scratch. g_pack per (b,s): [0..64) w, [64..192) e, [192..320) a
__device__ float g_pack[(size_t)NROWS * 320];
__device__ float g_r[(size_t)NROWS * DD];
__device__ float g_wf[IND * MM];   // Wr @ MK^T  [256,64]
__device__ float g_bf[MM];         // br @ MK^T  [64]

// ---------------- f32x2 helpers ----------------
__device__ __forceinline__ unsigned long long f2fma(unsigned long long a,
                                                    unsigned long long b,
                                                    unsigned long long c) {
    unsigned long long d;
    asm("fma.rn.f32x2 %0, %1, %2, %3;" : "=l"(d) : "l"(a), "l"(b), "l"(c));
    return d;
}
__device__ __forceinline__ unsigned long long f2add(unsigned long long a,
                                                    unsigned long long b) {
    unsigned long long d;
    asm("add.rn.f32x2 %0, %1, %2;" : "=l"(d) : "l"(a), "l"(b));
    return d;
}
__device__ __forceinline__ unsigned long long dup2(float x) {
    unsigned long long r;
    asm("mov.b64 %0, {%1, %1};" : "=l"(r) : "f"(x));
    return r;
}
__device__ __forceinline__ float lo32(unsigned long long v) {
    return __uint_as_float((unsigned)(v & 0xffffffffu));
}
__device__ __forceinline__ float hi32(unsigned long long v) {
    return __uint_as_float((unsigned)(v >> 32));
}

// ---------------- cp.async helpers ----------------
__device__ __forceinline__ uint32_t smem_u32(const void* p) {
    uint32_t a;
    asm("{ .reg .u64 tmp; cvta.to.shared.u64 tmp, %1; cvt.u32.u64 %0, tmp; }"
        : "=r"(a) : "l"(p));
    return a;
}
__device__ __forceinline__ void cp16(uint32_t s, const void* g) {
    asm volatile("cp.async.ca.shared.global [%0], [%1], 16;" :: "r"(s), "l"(g));
}
#define CP_COMMIT() asm volatile("cp.async.commit_group;" ::: "memory")
#define CP_WAIT1()  asm volatile("cp.async.wait_group 1;" ::: "memory")
#define CP_WAIT0()  asm volatile("cp.async.wait_group 0;" ::: "memory")

// ---------------- fast activations ----------------
__device__ __forceinline__ float fast_sigmoid(float v) {
    float t = __expf(-v);
    return __fdividef(1.0f, 1.0f + t);
}
__device__ __forceinline__ float fast_tanh(float v) {
    float t = __expf(fminf(2.0f * v, 80.0f));
    return __fdividef(t - 1.0f, t + 1.0f);
}

// =====================================================================
// Kernel 0: prep.  g_wf = Wr @ MK^T, g_bf = br @ MK^T.
// =====================================================================
__global__ __launch_bounds__(256) void prep_kernel(const float* __restrict__ Wr,
                                                   const float* __restrict__ br,
                                                   const float* __restrict__ mk) {
    int gid = blockIdx.x * 256 + threadIdx.x;
    int i = gid >> 6, m = gid & 63;
    float s = 0.f;
    const float* wr = Wr + i * 128;
    const float* mr = mk + m * 128;
#pragma unroll 4
    for (int d = 0; d < 128; d += 4) {
        float4 a = *(const float4*)(wr + d);
        float4 b = *(const float4*)(mr + d);
        s += a.x * b.x + a.y * b.y + a.z * b.z + a.w * b.w;
    }
    g_wf[i * 64 + m] = s;
    if (gid < 64) {
        float sb = 0.f;
        const float* mr2 = mk + gid * 128;
        for (int d = 0; d < 128; d++) sb += br[d] * mr2[d];
        g_bf[gid] = sb;
    }
}

// =====================================================================
// Kernel 1: FUSED projection (R11 known-good form). 128 rows, N=192.
// =====================================================================
__global__ __launch_bounds__(256) void proj_kernel(
    const float* __restrict__ x,
    const float* __restrict__ Ww, const float* __restrict__ bw) {
    __shared__ __align__(16) float As[16][132];
    __shared__ __align__(16) float Bs[16][200];

    const int row0 = blockIdx.x * 128;
    const int t = threadIdx.x;
    const int tm   = (t >> 4) * 8;
    const int tn_v = (t & 15) * 8;
    const int tn_w = (t & 15) * 4;

    unsigned long long accv[8][4];
    unsigned long long accw[8][2];
#pragma unroll
    for (int i = 0; i < 8; i++) {
#pragma unroll
        for (int j = 0; j < 4; j++) accv[i][j] = 0ULL;
        accw[i][0] = accw[i][1] = 0ULL;
    }

    for (int k0 = 0; k0 < IND; k0 += 16) {
#pragma unroll
        for (int i = 0; i < 2; i++) {
            int idx = t + i * 256;
            int m  = idx >> 2;
            int kq = (idx & 3) * 4;
            float4 v = *(const float4*)(x + (size_t)(row0 + m) * IND + k0 + kq);
            As[kq + 0][m] = v.x; As[kq + 1][m] = v.y;
            As[kq + 2][m] = v.z; As[kq + 3][m] = v.w;
        }
#pragma unroll
        for (int i = 0; i < 3; i++) {
            int idx = t + i * 256;
            int kk = idx / 48;
            int q4 = (idx - kk * 48) * 4;
            float4 v;
            if (q4 < 128) v = *(const float4*)(Ww + (size_t)(k0 + kk) * 128 + q4);
            else          v = *(const float4*)(g_wf + (size_t)(k0 + kk) * 64 + (q4 - 128));
            *(float4*)&Bs[kk][q4] = v;
        }
        __syncthreads();
#pragma unroll
        for (int kk = 0; kk < 16; kk++) {
            float a[8];
            *(float4*)(a)     = *(const float4*)&As[kk][tm];
            *(float4*)(a + 4) = *(const float4*)&As[kk][tm + 4];
            unsigned long long bv[4], bw2[2];
            *(ulonglong2*)(bv)     = *(const ulonglong2*)&Bs[kk][tn_v];
            *(ulonglong2*)(bv + 2) = *(const ulonglong2*)&Bs[kk][tn_v + 4];
            *(ulonglong2*)(bw2)    = *(const ulonglong2*)&Bs[kk][128 + tn_w];
#pragma unroll
            for (int i = 0; i < 8; i++) {
                unsigned long long ad = dup2(a[i]);
#pragma unroll
                for (int j = 0; j < 4; j++) accv[i][j] = f2fma(ad, bv[j], accv[i][j]);
                accw[i][0] = f2fma(ad, bw2[0], accw[i][0]);
                accw[i][1] = f2fma(ad, bw2[1], accw[i][1]);
            }
        }
        __syncthreads();
    }

    float bbv[8], bbw[4];
    *(float4*)(bbv)     = *(const float4*)(bw + tn_v);
    *(float4*)(bbv + 4) = *(const float4*)(bw + tn_v + 4);
    *(float4*)(bbw)     = *(const float4*)(g_bf + tn_w);

#pragma unroll
    for (int i = 0; i < 8; i++) {
        size_t row = (size_t)(row0 + tm + i);
        float* pr = g_pack + row * 320;
        {
            float e[8], av[8];
#pragma unroll
            for (int j = 0; j < 4; j++) {
                float v0 = lo32(accv[i][j]) + bbv[2 * j];
                float v1 = hi32(accv[i][j]) + bbv[2 * j + 1];
                e[2 * j]      = fast_sigmoid(v0);
                e[2 * j + 1]  = fast_sigmoid(v1);
                av[2 * j]     = fast_tanh(v0);
                av[2 * j + 1] = fast_tanh(v1);
            }
            *(float4*)(pr + 64 + tn_v)      = *(float4*)(e);
            *(float4*)(pr + 64 + tn_v + 4)  = *(float4*)(e + 4);
            *(float4*)(pr + 192 + tn_v)     = *(float4*)(av);
            *(float4*)(pr + 192 + tn_v + 4) = *(float4*)(av + 4);
        }
        {
            float v[4];
            v[0] = lo32(accw[i][0]) + bbw[0];
            v[1] = hi32(accw[i][0]) + bbw[1];
            v[2] = lo32(accw[i][1]) + bbw[2];
            v[3] = hi32(accw[i][1]) + bbw[3];
            float mx = fmaxf(fmaxf(v[0], v[1]), fmaxf(v[2], v[3]));
            mx = fmaxf(mx, __shfl_xor_sync(0xffffffffu, mx, 1));
            mx = fmaxf(mx, __shfl_xor_sync(0xffffffffu, mx, 2));
            mx = fmaxf(mx, __shfl_xor_sync(0xffffffffu, mx, 4));
            mx = fmaxf(mx, __shfl_xor_sync(0xffffffffu, mx, 8));
            float s = 0.f;
#pragma unroll
            for (int j = 0; j < 4; j++) { v[j] = __expf(v[j] - mx); s += v[j]; }
            s += __shfl_xor_sync(0xffffffffu, s, 1);
            s += __shfl_xor_sync(0xffffffffu, s, 2);
            s += __shfl_xor_sync(0xffffffffu, s, 4);
            s += __shfl_xor_sync(0xffffffffu, s, 8);
            float inv = __fdividef(1.0f, s);
#pragma unroll
            for (int j = 0; j < 4; j++) v[j] *= inv;
            *(float4*)(pr + tn_w) = *(float4*)(v);
        }
    }
}

// =====================================================================
// Kernel 3: scan v6.2. As v6.1 plus w prefetched one step ahead
// (registers are free at 1 CTA/SM).
// =====================================================================
#define CH 16
__device__ __forceinline__ void stage_store7(float (*buf)[400], const float* v) {
    const int t = threadIdx.x;
#pragma unroll
    for (int k = 0; k < 20; k++) {
        int idx = t + 256 * k;
        int q = idx / 320;
        int j = idx - q * 320;
        if (j < 64) {
            int pos = 2 * j + 4 * (j >> 4);
            buf[q][pos]     = v[k];
            buf[q][pos + 1] = v[k];
        } else {
            buf[q][j + 80] = v[k];
        }
    }
}

__global__ __launch_bounds__(256) void scan_kernel(const float* __restrict__ mv0,
                                                   float* __restrict__ rout) {
    __shared__ __align__(16) float sbuf[2][CH][400];
    const int b  = blockIdx.x;
    const int t  = threadIdx.x;
    const int dp = t >> 2;
    const int mq = t & 3;
    const int m0 = mq * 16;
    const int wbase = mq * 36;

    unsigned long long Mv[16];
#pragma unroll
    for (int i = 0; i < 16; i++)
        Mv[i] = *(const unsigned long long*)(mv0 + (m0 + i) * 128 + 2 * dp);

    const float* pk = g_pack + (size_t)b * (SS * 320);
    float stg[20];
#pragma unroll
    for (int k = 0; k < 20; k++) stg[k] = pk[t + 256 * k];
    stage_store7(sbuf[0], stg);
    __syncthreads();

    float* rb = rout + (size_t)b * (SS * 128) + 2 * dp;
    const int NCHUNK = SS / CH;

    for (int c = 0; c < NCHUNK; c++) {
        const int pb = c & 1;
        const bool more = (c + 1 < NCHUNK);
        if (more) {
            const float* pn = pk + (size_t)(c + 1) * (CH * 320);
#pragma unroll
            for (int k = 0; k < 20; k++) stg[k] = pn[t + 256 * k];
        }
        // preload step 0 operands
        unsigned long long e2 = *(const unsigned long long*)(&sbuf[pb][0][144 + 2 * dp]);
        unsigned long long a2 = *(const unsigned long long*)(&sbuf[pb][0][272 + 2 * dp]);
        ulonglong2 wc[8];
        {
            const float* wp0 = sbuf[pb][0] + wbase;
#pragma unroll
            for (int j = 0; j < 8; j++) wc[j] = *(const ulonglong2*)(wp0 + 4 * j);
        }
#pragma unroll
        for (int q = 0; q < CH; q++) {
            // prefetch next step operands
            unsigned long long e2n = 0ULL, a2n = 0ULL;
            ulonglong2 wn[8];
            if (q + 1 < CH) {
                const float* bqn = sbuf[pb][q + 1];
                e2n = *(const unsigned long long*)(bqn + 144 + 2 * dp);
                a2n = *(const unsigned long long*)(bqn + 272 + 2 * dp);
                const float* wpn = bqn + wbase;
#pragma unroll
                for (int j = 0; j < 8; j++) wn[j] = *(const ulonglong2*)(wpn + 4 * j);
            } else {
#pragma unroll
                for (int j = 0; j < 8; j++) { wn[j].x = 0ULL; wn[j].y = 0ULL; }
            }
            unsigned long long ne2 = e2 ^ 0x8000000080000000ULL;
            unsigned long long racc[4] = {0ULL, 0ULL, 0ULL, 0ULL};
#pragma unroll
            for (int j = 0; j < 8; j++) {
                racc[j & 3] = f2fma(wc[j].x, Mv[2 * j], racc[j & 3]);
                unsigned long long t0 = f2fma(ne2, Mv[2 * j], a2);
                Mv[2 * j] = f2fma(wc[j].x, t0, Mv[2 * j]);
                racc[(j + 2) & 3] = f2fma(wc[j].y, Mv[2 * j + 1], racc[(j + 2) & 3]);
                unsigned long long t1 = f2fma(ne2, Mv[2 * j + 1], a2);
                Mv[2 * j + 1] = f2fma(wc[j].y, t1, Mv[2 * j + 1]);
            }
            unsigned long long r2 = f2add(f2add(racc[0], racc[1]),
                                          f2add(racc[2], racc[3]));
            float rx = lo32(r2);
            float ry = hi32(r2);
            rx += __shfl_xor_sync(0xffffffffu, rx, 1);
            ry += __shfl_xor_sync(0xffffffffu, ry, 1);
            rx += __shfl_xor_sync(0xffffffffu, rx, 2);
            ry += __shfl_xor_sync(0xffffffffu, ry, 2);
            if (mq == 0) {
                float2 rv; rv.x = rx; rv.y = ry;
                *(float2*)(rb + (size_t)(c * CH + q) * 128) = rv;
            }
            e2 = e2n; a2 = a2n;
#pragma unroll
            for (int j = 0; j < 8; j++) wc[j] = wn[j];
        }
        if (more) stage_store7(sbuf[pb ^ 1], stg);
        __syncthreads();
    }
}

// =====================================================================
// Kernel 4: out, cp.async double-buffered, 2 CTAs/SM enforced.
// A m-major As[pb][128][20]; B Bs[pb][16][128]. K=128, 8 chunks.
// =====================================================================
__global__ __launch_bounds__(256, 2) void out_kernel(const float* __restrict__ Wp,
                                                     const float* __restrict__ bp,
                                                     float* __restrict__ out) {
    __shared__ __align__(16) float As[2][128][20];
    __shared__ __align__(16) float Bs[2][16][128];
    const int row0 = blockIdx.x * 128;
    const int t = threadIdx.x;
    const int tm = (t >> 4) * 8;
    const int tn = (t & 15) * 8;

    // staging addresses (computed once)
    const int mA = t >> 2, c4 = (t & 3) * 4;
    const int kkB = t >> 5, nqB = (t & 31) * 4;
    const float* gA0 = g_r + (size_t)(row0 + mA) * DD + c4;
    const float* gA1 = gA0 + (size_t)64 * DD;
    const float* gB0 = Wp + (size_t)kkB * 128 + nqB;
    const float* gB1 = gB0 + 8 * 128;
    const uint32_t sA0 = smem_u32(&As[0][mA][c4]);
    const uint32_t sA1 = smem_u32(&As[0][mA + 64][c4]);
    const uint32_t sB0 = smem_u32(&Bs[0][kkB][nqB]);
    const uint32_t sB1 = smem_u32(&Bs[0][kkB + 8][nqB]);
    const uint32_t ABUF = 128 * 20 * 4;
    const uint32_t BBUF = 16 * 128 * 4;

    unsigned long long acc2[8][4];
#pragma unroll
    for (int i = 0; i < 8; i++)
#pragma unroll
        for (int j = 0; j < 4; j++) acc2[i][j] = 0ULL;

    // prologue: stage chunk 0 into buffer 0
    cp16(sA0, gA0);
    cp16(sA1, gA1);
    cp16(sB0, gB0);
    cp16(sB1, gB1);
    CP_COMMIT();

    const int NC = DD / 16;
    for (int c = 0; c < NC; c++) {
        const int pb = c & 1;
        if (c + 1 < NC) {
            const int k0n = (c + 1) * 16;
            const uint32_t ao = (pb ^ 1) * ABUF;
            const uint32_t bo = (pb ^ 1) * BBUF;
            cp16(sA0 + ao, gA0 + k0n);
            cp16(sA1 + ao, gA1 + k0n);
            cp16(sB0 + bo, gB0 + (size_t)k0n * 128);
            cp16(sB1 + bo, gB1 + (size_t)k0n * 128);
            CP_COMMIT();
            CP_WAIT1();
        } else {
            CP_WAIT0();
        }
        __syncthreads();
#pragma unroll
        for (int kk = 0; kk < 16; kk++) {
            float a[8];
#pragma unroll
            for (int i = 0; i < 8; i++) a[i] = As[pb][tm + i][kk];
            unsigned long long b2[4];
            *(ulonglong2*)(b2)     = *(const ulonglong2*)&Bs[pb][kk][tn];
            *(ulonglong2*)(b2 + 2) = *(const ulonglong2*)&Bs[pb][kk][tn + 4];
#pragma unroll
            for (int i = 0; i < 8; i++) {
                unsigned long long ad = dup2(a[i]);
#pragma unroll
                for (int j = 0; j < 4; j++) acc2[i][j] = f2fma(ad, b2[j], acc2[i][j]);
            }
        }
        __syncthreads();
    }

    float bb[8];
    *(float4*)(bb)     = *(const float4*)(bp + tn);
    *(float4*)(bb + 4) = *(const float4*)(bp + tn + 4);
#pragma unroll
    for (int i = 0; i < 8; i++) {
        size_t row = (size_t)(row0 + tm + i);
        float o[8];
#pragma unroll
        for (int j = 0; j < 4; j++) {
            o[2 * j]     = fast_sigmoid(lo32(acc2[i][j]) + bb[2 * j]);
            o[2 * j + 1] = fast_sigmoid(hi32(acc2[i][j]) + bb[2 * j + 1]);
        }
        *(float4*)(out + row * OUTD + tn)     = *(float4*)(o);
        *(float4*)(out + row * OUTD + tn + 4) = *(float4*)(o + 4);
    }
}

// =====================================================================
// Launch
// =====================================================================
extern "C" void kernel_launch(void* const* d_in, const int* in_sizes, int n_in,
                              void* d_out, int out_size) {
    const float* x   = (const float*)d_in[0];
    const float* mk  = (const float*)d_in[1];
    const float* mv  = (const float*)d_in[2];
    const float* Wr  = (const float*)d_in[3];
    const float* br  = (const float*)d_in[4];
    const float* Ww  = (const float*)d_in[5];
    const float* bw  = (const float*)d_in[6];
    const float* Wp  = (const float*)d_in[7];
    const float* bp  = (const float*)d_in[8];
    float* out = (float*)d_out;

    float* gr;
    cudaGetSymbolAddress((void**)&gr, g_r);

    prep_kernel<<<64, 256>>>(Wr, br, mk);
    proj_kernel<<<NROWS / 128, 256>>>(x, Ww, bw);
    scan_kernel<<<BB, 256>>>(mv, gr);
    out_kernel<<<NROWS / 128, 256>>>(Wp, bp, out);
}

// round 15
// speedup vs baseline: 1.0332x; 1.0332x over previous
#include <cuda_runtime.h>
#include <cuda_bf16.h>
#include <math.h>
#include <stdint.h>

// Problem constants
#define BB 128
#define SS 1024
#define IND 256
#define DD 128
#define MM 64
#define OUTD 128
#define NROWS (BB * SS)   // 131072

// Scratch. g_pack per (b,s): [0..64) w, [64..192) e, [192..320) a
__device__ float g_pack[(size_t)NROWS * 320];
__device__ float g_r[(size_t)NROWS * DD];
__device__ float g_wf[IND * MM];   // Wr @ MK^T  [256,64]
__device__ float g_bf[MM];         // br @ MK^T  [64]

// ---------------- f32x2 helpers ----------------
__device__ __forceinline__ unsigned long long f2fma(unsigned long long a,
                                                    unsigned long long b,
                                                    unsigned long long c) {
    unsigned long long d;
    asm("fma.rn.f32x2 %0, %1, %2, %3;" : "=l"(d) : "l"(a), "l"(b), "l"(c));
    return d;
}
__device__ __forceinline__ unsigned long long f2add(unsigned long long a,
                                                    unsigned long long b) {
    unsigned long long d;
    asm("add.rn.f32x2 %0, %1, %2;" : "=l"(d) : "l"(a), "l"(b));
    return d;
}
__device__ __forceinline__ unsigned long long dup2(float x) {
    unsigned long long r;
    asm("mov.b64 %0, {%1, %1};" : "=l"(r) : "f"(x));
    return r;
}
__device__ __forceinline__ unsigned long long pack2(float x, float y) {
    unsigned long long r;
    asm("mov.b64 %0, {%1, %2};" : "=l"(r) : "f"(x), "f"(y));
    return r;
}
__device__ __forceinline__ float lo32(unsigned long long v) {
    return __uint_as_float((unsigned)(v & 0xffffffffu));
}
__device__ __forceinline__ float hi32(unsigned long long v) {
    return __uint_as_float((unsigned)(v >> 32));
}

// ---------------- fast activations ----------------
__device__ __forceinline__ float fast_sigmoid(float v) {
    float t = __expf(-v);
    return __fdividef(1.0f, 1.0f + t);
}
__device__ __forceinline__ float fast_tanh(float v) {
    float t = __expf(fminf(2.0f * v, 80.0f));
    return __fdividef(t - 1.0f, t + 1.0f);
}

// =====================================================================
// Kernel 0: prep.  g_wf = Wr @ MK^T, g_bf = br @ MK^T.
// =====================================================================
__global__ __launch_bounds__(256) void prep_kernel(const float* __restrict__ Wr,
                                                   const float* __restrict__ br,
                                                   const float* __restrict__ mk) {
    int gid = blockIdx.x * 256 + threadIdx.x;
    int i = gid >> 6, m = gid & 63;
    float s = 0.f;
    const float* wr = Wr + i * 128;
    const float* mr = mk + m * 128;
#pragma unroll 4
    for (int d = 0; d < 128; d += 4) {
        float4 a = *(const float4*)(wr + d);
        float4 b = *(const float4*)(mr + d);
        s += a.x * b.x + a.y * b.y + a.z * b.z + a.w * b.w;
    }
    g_wf[i * 64 + m] = s;
    if (gid < 64) {
        float sb = 0.f;
        const float* mr2 = mk + gid * 128;
        for (int d = 0; d < 128; d++) sb += br[d] * mr2[d];
        g_bf[gid] = sb;
    }
}

// =====================================================================
// Kernel 1: FUSED projection, BK=32 (8 barrier-pairs). 128 rows, N=192.
// Accumulators pre-initialized with biases.
// =====================================================================
__global__ __launch_bounds__(256) void proj_kernel(
    const float* __restrict__ x,
    const float* __restrict__ Ww, const float* __restrict__ bw) {
    __shared__ __align__(16) float As[32][132];
    __shared__ __align__(16) float Bs[32][200];

    const int row0 = blockIdx.x * 128;
    const int t = threadIdx.x;
    const int tm   = (t >> 4) * 8;
    const int tn_v = (t & 15) * 8;
    const int tn_w = (t & 15) * 4;

    unsigned long long accv[8][4];
    unsigned long long accw[8][2];
    {
        float bbv[8], bbw[4];
        *(float4*)(bbv)     = *(const float4*)(bw + tn_v);
        *(float4*)(bbv + 4) = *(const float4*)(bw + tn_v + 4);
        *(float4*)(bbw)     = *(const float4*)(g_bf + tn_w);
#pragma unroll
        for (int i = 0; i < 8; i++) {
#pragma unroll
            for (int j = 0; j < 4; j++)
                accv[i][j] = pack2(bbv[2 * j], bbv[2 * j + 1]);
            accw[i][0] = pack2(bbw[0], bbw[1]);
            accw[i][1] = pack2(bbw[2], bbw[3]);
        }
    }

    for (int k0 = 0; k0 < IND; k0 += 32) {
        // A tile: x[row0..+128, k0..+32] -> As[k][m] transposed (4 float4/thread)
#pragma unroll
        for (int i = 0; i < 4; i++) {
            int idx = t + i * 256;          // 0..1023
            int m  = idx >> 3;              // 0..127
            int kq = (idx & 7) * 4;         // 0..28
            float4 v = *(const float4*)(x + (size_t)(row0 + m) * IND + k0 + kq);
            As[kq + 0][m] = v.x; As[kq + 1][m] = v.y;
            As[kq + 2][m] = v.z; As[kq + 3][m] = v.w;
        }
        // B tile: 32k x 192n (6 float4/thread)
#pragma unroll
        for (int i = 0; i < 6; i++) {
            int idx = t + i * 256;          // 0..1535
            int kk = idx / 48;
            int q4 = (idx - kk * 48) * 4;
            float4 v;
            if (q4 < 128) v = *(const float4*)(Ww + (size_t)(k0 + kk) * 128 + q4);
            else          v = *(const float4*)(g_wf + (size_t)(k0 + kk) * 64 + (q4 - 128));
            *(float4*)&Bs[kk][q4] = v;
        }
        __syncthreads();
#pragma unroll
        for (int kk = 0; kk < 32; kk++) {
            float a[8];
            *(float4*)(a)     = *(const float4*)&As[kk][tm];
            *(float4*)(a + 4) = *(const float4*)&As[kk][tm + 4];
            unsigned long long bv[4], bw2[2];
            *(ulonglong2*)(bv)     = *(const ulonglong2*)&Bs[kk][tn_v];
            *(ulonglong2*)(bv + 2) = *(const ulonglong2*)&Bs[kk][tn_v + 4];
            *(ulonglong2*)(bw2)    = *(const ulonglong2*)&Bs[kk][128 + tn_w];
#pragma unroll
            for (int i = 0; i < 8; i++) {
                unsigned long long ad = dup2(a[i]);
#pragma unroll
                for (int j = 0; j < 4; j++) accv[i][j] = f2fma(ad, bv[j], accv[i][j]);
                accw[i][0] = f2fma(ad, bw2[0], accw[i][0]);
                accw[i][1] = f2fma(ad, bw2[1], accw[i][1]);
            }
        }
        __syncthreads();
    }

#pragma unroll
    for (int i = 0; i < 8; i++) {
        size_t row = (size_t)(row0 + tm + i);
        float* pr = g_pack + row * 320;
        {
            float e[8], av[8];
#pragma unroll
            for (int j = 0; j < 4; j++) {
                float v0 = lo32(accv[i][j]);
                float v1 = hi32(accv[i][j]);
                e[2 * j]      = fast_sigmoid(v0);
                e[2 * j + 1]  = fast_sigmoid(v1);
                av[2 * j]     = fast_tanh(v0);
                av[2 * j + 1] = fast_tanh(v1);
            }
            *(float4*)(pr + 64 + tn_v)      = *(float4*)(e);
            *(float4*)(pr + 64 + tn_v + 4)  = *(float4*)(e + 4);
            *(float4*)(pr + 192 + tn_v)     = *(float4*)(av);
            *(float4*)(pr + 192 + tn_v + 4) = *(float4*)(av + 4);
        }
        {
            float v[4];
            v[0] = lo32(accw[i][0]);
            v[1] = hi32(accw[i][0]);
            v[2] = lo32(accw[i][1]);
            v[3] = hi32(accw[i][1]);
            float mx = fmaxf(fmaxf(v[0], v[1]), fmaxf(v[2], v[3]));
            mx = fmaxf(mx, __shfl_xor_sync(0xffffffffu, mx, 1));
            mx = fmaxf(mx, __shfl_xor_sync(0xffffffffu, mx, 2));
            mx = fmaxf(mx, __shfl_xor_sync(0xffffffffu, mx, 4));
            mx = fmaxf(mx, __shfl_xor_sync(0xffffffffu, mx, 8));
            float s = 0.f;
#pragma unroll
            for (int j = 0; j < 4; j++) { v[j] = __expf(v[j] - mx); s += v[j]; }
            s += __shfl_xor_sync(0xffffffffu, s, 1);
            s += __shfl_xor_sync(0xffffffffu, s, 2);
            s += __shfl_xor_sync(0xffffffffu, s, 4);
            s += __shfl_xor_sync(0xffffffffu, s, 8);
            float inv = __fdividef(1.0f, s);
#pragma unroll
            for (int j = 0; j < 4; j++) v[j] *= inv;
            *(float4*)(pr + tn_w) = *(float4*)(v);
        }
    }
}

// =====================================================================
// Kernel 3: scan v6.1 (R11 exact — best measured ~228us).
// =====================================================================
#define CH 16
__device__ __forceinline__ void stage_store7(float (*buf)[400], const float* v) {
    const int t = threadIdx.x;
#pragma unroll
    for (int k = 0; k < 20; k++) {
        int idx = t + 256 * k;
        int q = idx / 320;
        int j = idx - q * 320;
        if (j < 64) {
            int pos = 2 * j + 4 * (j >> 4);
            buf[q][pos]     = v[k];
            buf[q][pos + 1] = v[k];
        } else {
            buf[q][j + 80] = v[k];
        }
    }
}

__global__ __launch_bounds__(256) void scan_kernel(const float* __restrict__ mv0,
                                                   float* __restrict__ rout) {
    __shared__ __align__(16) float sbuf[2][CH][400];
    const int b  = blockIdx.x;
    const int t  = threadIdx.x;
    const int dp = t >> 2;
    const int mq = t & 3;
    const int m0 = mq * 16;
    const int wbase = mq * 36;

    unsigned long long Mv[16];
#pragma unroll
    for (int i = 0; i < 16; i++)
        Mv[i] = *(const unsigned long long*)(mv0 + (m0 + i) * 128 + 2 * dp);

    const float* pk = g_pack + (size_t)b * (SS * 320);
    float stg[20];
#pragma unroll
    for (int k = 0; k < 20; k++) stg[k] = pk[t + 256 * k];
    stage_store7(sbuf[0], stg);
    __syncthreads();

    float* rb = rout + (size_t)b * (SS * 128) + 2 * dp;
    const int NCHUNK = SS / CH;

    for (int c = 0; c < NCHUNK; c++) {
        const int pb = c & 1;
        const bool more = (c + 1 < NCHUNK);
        if (more) {
            const float* pn = pk + (size_t)(c + 1) * (CH * 320);
#pragma unroll
            for (int k = 0; k < 20; k++) stg[k] = pn[t + 256 * k];
        }
        // prefetch e/a of step 0
        unsigned long long e2 = *(const unsigned long long*)(&sbuf[pb][0][144 + 2 * dp]);
        unsigned long long a2 = *(const unsigned long long*)(&sbuf[pb][0][272 + 2 * dp]);
#pragma unroll
        for (int q = 0; q < CH; q++) {
            const float* bq = sbuf[pb][q];
            unsigned long long e2n = 0ULL, a2n = 0ULL;
            if (q + 1 < CH) {
                const float* bqn = sbuf[pb][q + 1];
                e2n = *(const unsigned long long*)(bqn + 144 + 2 * dp);
                a2n = *(const unsigned long long*)(bqn + 272 + 2 * dp);
            }
            unsigned long long ne2 = e2 ^ 0x8000000080000000ULL;
            unsigned long long racc[4] = {0ULL, 0ULL, 0ULL, 0ULL};
            const float* wp = bq + wbase;
#pragma unroll
            for (int i = 0; i < 16; i += 2) {
                ulonglong2 wv = *(const ulonglong2*)(wp + 2 * i);
                racc[(i >> 1) & 3] = f2fma(wv.x, Mv[i], racc[(i >> 1) & 3]);
                unsigned long long t0 = f2fma(ne2, Mv[i], a2);
                Mv[i] = f2fma(wv.x, t0, Mv[i]);
                racc[((i >> 1) + 2) & 3] = f2fma(wv.y, Mv[i + 1], racc[((i >> 1) + 2) & 3]);
                unsigned long long t1 = f2fma(ne2, Mv[i + 1], a2);
                Mv[i + 1] = f2fma(wv.y, t1, Mv[i + 1]);
            }
            unsigned long long r2 = f2add(f2add(racc[0], racc[1]),
                                          f2add(racc[2], racc[3]));
            float rx = lo32(r2);
            float ry = hi32(r2);
            rx += __shfl_xor_sync(0xffffffffu, rx, 1);
            ry += __shfl_xor_sync(0xffffffffu, ry, 1);
            rx += __shfl_xor_sync(0xffffffffu, rx, 2);
            ry += __shfl_xor_sync(0xffffffffu, ry, 2);
            if (mq == 0) {
                float2 rv; rv.x = rx; rv.y = ry;
                *(float2*)(rb + (size_t)(c * CH + q) * 128) = rv;
            }
            e2 = e2n; a2 = a2n;
        }
        if (more) stage_store7(sbuf[pb ^ 1], stg);
        __syncthreads();
    }
}

// =====================================================================
// Kernel 4: y = sigmoid(r @ Wp + bp) with f32x2 (R9/R11 form, 110us).
// =====================================================================
__global__ __launch_bounds__(256) void out_kernel(const float* __restrict__ Wp,
                                                  const float* __restrict__ bp,
                                                  float* __restrict__ out) {
    __shared__ __align__(16) float As[16][132];
    __shared__ __align__(16) float Bs[16][128];
    const int row0 = blockIdx.x * 128;
    const int t = threadIdx.x;
    const int tm = (t >> 4) * 8;
    const int tn = (t & 15) * 8;

    unsigned long long acc2[8][4];
    {
        float bb[8];
        *(float4*)(bb)     = *(const float4*)(bp + tn);
        *(float4*)(bb + 4) = *(const float4*)(bp + tn + 4);
#pragma unroll
        for (int i = 0; i < 8; i++)
#pragma unroll
            for (int j = 0; j < 4; j++)
                acc2[i][j] = pack2(bb[2 * j], bb[2 * j + 1]);
    }

    for (int k0 = 0; k0 < DD; k0 += 16) {
#pragma unroll
        for (int i = 0; i < 2; i++) {
            int idx = t + i * 256;
            int m  = idx >> 2;
            int kq = (idx & 3) * 4;
            float4 v = *(const float4*)(g_r + (size_t)(row0 + m) * DD + k0 + kq);
            As[kq + 0][m] = v.x; As[kq + 1][m] = v.y;
            As[kq + 2][m] = v.z; As[kq + 3][m] = v.w;
        }
#pragma unroll
        for (int i = 0; i < 2; i++) {
            int idx = t + i * 256;
            int kk = idx >> 5;
            int nq = (idx & 31) * 4;
            *(float4*)&Bs[kk][nq] = *(const float4*)(Wp + (size_t)(k0 + kk) * 128 + nq);
        }
        __syncthreads();
#pragma unroll
        for (int kk = 0; kk < 16; kk++) {
            float a[8];
            *(float4*)(a)     = *(const float4*)&As[kk][tm];
            *(float4*)(a + 4) = *(const float4*)&As[kk][tm + 4];
            unsigned long long b2[4];
            *(ulonglong2*)(b2)     = *(const ulonglong2*)&Bs[kk][tn];
            *(ulonglong2*)(b2 + 2) = *(const ulonglong2*)&Bs[kk][tn + 4];
#pragma unroll
            for (int i = 0; i < 8; i++) {
                unsigned long long ad = dup2(a[i]);
#pragma unroll
                for (int j = 0; j < 4; j++) acc2[i][j] = f2fma(ad, b2[j], acc2[i][j]);
            }
        }
        __syncthreads();
    }

#pragma unroll
    for (int i = 0; i < 8; i++) {
        size_t row = (size_t)(row0 + tm + i);
        float o[8];
#pragma unroll
        for (int j = 0; j < 4; j++) {
            o[2 * j]     = fast_sigmoid(lo32(acc2[i][j]));
            o[2 * j + 1] = fast_sigmoid(hi32(acc2[i][j]));
        }
        *(float4*)(out + row * OUTD + tn)     = *(float4*)(o);
        *(float4*)(out + row * OUTD + tn + 4) = *(float4*)(o + 4);
    }
}

// =====================================================================
// Launch
// =====================================================================
extern "C" void kernel_launch(void* const* d_in, const int* in_sizes, int n_in,
                              void* d_out, int out_size) {
    const float* x   = (const float*)d_in[0];
    const float* mk  = (const float*)d_in[1];
    const float* mv  = (const float*)d_in[2];
    const float* Wr  = (const float*)d_in[3];
    const float* br  = (const float*)d_in[4];
    const float* Ww  = (const float*)d_in[5];
    const float* bw  = (const float*)d_in[6];
    const float* Wp  = (const float*)d_in[7];
    const float* bp  = (const float*)d_in[8];
    float* out = (float*)d_out;

    float* gr;
    cudaGetSymbolAddress((void**)&gr, g_r);

    prep_kernel<<<64, 256>>>(Wr, br, mk);
    proj_kernel<<<NROWS / 128, 256>>>(x, Ww, bw);
    scan_kernel<<<BB, 256>>>(mv, gr);
    out_kernel<<<NROWS / 128, 256>>>(Wp, bp, out);
}